// round 8
// baseline (speedup 1.0000x reference)
#include <cuda_runtime.h>
#include <cuda_bf16.h>
#include <cuda_fp16.h>
#include <math.h>

#define Bc  4
#define Nc  2048
#define Cc  256
#define Hc  8
#define Dhc 32

__device__ float g_q[Bc * Nc * Cc];
__device__ float g_k[Bc * Nc * Cc];
__device__ float g_v[Bc * Nc * Cc];
__device__ float g_x[Bc * Nc * Cc];
__device__ float g_maskT[(size_t)Bc * Nc * Nc];
__device__ __half g_p[(size_t)Bc * Hc * Nc * Nc];   // unnormalized exp2(S) stash

__device__ __forceinline__ float to_tf32(float x) {
    asm("cvt.rna.tf32.f32 %0, %1;" : "=f"(x) : "f"(x));
    return x;
}
__device__ __forceinline__ float ex2f(float x) {
    float y;
    asm("ex2.approx.ftz.f32 %0, %1;" : "=f"(y) : "f"(x));
    return y;
}
__device__ __forceinline__ void mma8(float d[4], float a0, float a1, float a2, float a3,
                                     float b0, float b1) {
    asm volatile(
        "mma.sync.aligned.m16n8k8.row.col.f32.tf32.tf32.f32 "
        "{%0,%1,%2,%3}, {%4,%5,%6,%7}, {%8,%9}, {%0,%1,%2,%3};"
        : "+f"(d[0]), "+f"(d[1]), "+f"(d[2]), "+f"(d[3])
        : "r"(__float_as_uint(a0)), "r"(__float_as_uint(a1)),
          "r"(__float_as_uint(a2)), "r"(__float_as_uint(a3)),
          "r"(__float_as_uint(b0)), "r"(__float_as_uint(b1)));
}
__device__ __forceinline__ void mma16bf(float d[4], unsigned a0, unsigned a1, unsigned a2,
                                        unsigned a3, unsigned b0, unsigned b1) {
    asm volatile(
        "mma.sync.aligned.m16n8k16.row.col.f32.bf16.bf16.f32 "
        "{%0,%1,%2,%3}, {%4,%5,%6,%7}, {%8,%9}, {%0,%1,%2,%3};"
        : "+f"(d[0]), "+f"(d[1]), "+f"(d[2]), "+f"(d[3])
        : "r"(a0), "r"(a1), "r"(a2), "r"(a3), "r"(b0), "r"(b1));
}
__device__ __forceinline__ float* bufsel(int s) {
    switch (s) {
        case 0: return g_q;
        case 1: return g_k;
        case 2: return g_v;
        default: return g_x;
    }
}

__global__ void init_kernel() {                    // launch-slot filler (g_x fully rewritten later)
    g_x[threadIdx.x] = 0.f;
}

// maskT[b][q][k] = mask[b][k][q] / max_k mask[b][k][q]
__global__ __launch_bounds__(256) void mask_prep_kernel(const float* __restrict__ mask) {
    const int qt = blockIdx.x, b = blockIdx.y;
    const int q0 = qt * 64, t = threadIdx.x;
    __shared__ float red[4][64];
    __shared__ float cinv[64];
    __shared__ float ts[64][65];
    const int qj = t & 63, kr = t >> 6;
    const float* mb = mask + (size_t)b * Nc * Nc;

    float lmax = 0.f;
    for (int k = kr; k < Nc; k += 4)
        lmax = fmaxf(lmax, mb[(size_t)k * Nc + q0 + qj]);
    red[kr][qj] = lmax;
    __syncthreads();
    if (t < 64)
        cinv[t] = 1.0f / fmaxf(fmaxf(red[0][t], red[1][t]), fmaxf(red[2][t], red[3][t]));
    __syncthreads();

    float* mtb = g_maskT + (size_t)b * Nc * Nc;
    for (int k0 = 0; k0 < Nc; k0 += 64) {
        #pragma unroll 4
        for (int ii = 0; ii < 16; ii++) {
            int i = kr + 4 * ii;
            ts[i][qj] = mb[(size_t)(k0 + i) * Nc + q0 + qj];
        }
        __syncthreads();
        #pragma unroll 4
        for (int jj = 0; jj < 16; jj++) {
            int j = kr + 4 * jj;
            mtb[(size_t)(q0 + j) * Nc + k0 + qj] = ts[qj][j] * cinv[j];
        }
        __syncthreads();
    }
}

// Out[m][n] = (sum_k A[m][k]*W[n][k] + bias[n])*scale + resid[m][n]
__global__ __launch_bounds__(128) void gemm_kernel(
    const float* __restrict__ Aext, int asel,
    const float* __restrict__ W, const float* __restrict__ bias,
    const float* __restrict__ resid,
    float* __restrict__ Oext, int osel, float scale)
{
    const int Kd = Cc, Nd = Cc;
    const float* A = (asel >= 0) ? bufsel(asel) : Aext;
    float* Out = (osel >= 0) ? bufsel(osel) : Oext;

    const int m0 = blockIdx.x * 64, n0 = blockIdx.y * 64;
    __shared__ float As[64][36];
    __shared__ float Ws[64][36];
    const int tid = threadIdx.x, warp = tid >> 5, lane = tid & 31;
    const int wq = warp >> 1, wn = warp & 1, lg = lane >> 2, lr = lane & 3;
    const int r = tid >> 1, cs = (tid & 1) * 16;

    float acc[2][4][4];
    #pragma unroll
    for (int a = 0; a < 2; a++)
        #pragma unroll
        for (int bb = 0; bb < 4; bb++)
            #pragma unroll
            for (int c = 0; c < 4; c++) acc[a][bb][c] = 0.f;

    for (int k0 = 0; k0 < Kd; k0 += 32) {
        __syncthreads();
        const float4* pa = (const float4*)(A + (size_t)(m0 + r) * Kd + k0 + cs);
        const float4* pw = (const float4*)(W + (size_t)(n0 + r) * Kd + k0 + cs);
        #pragma unroll
        for (int i = 0; i < 4; i++) {
            float4 v = pa[i];
            v.x = to_tf32(v.x); v.y = to_tf32(v.y); v.z = to_tf32(v.z); v.w = to_tf32(v.w);
            *(float4*)&As[r][cs + 4 * i] = v;
            float4 w = pw[i];
            w.x = to_tf32(w.x); w.y = to_tf32(w.y); w.z = to_tf32(w.z); w.w = to_tf32(w.w);
            *(float4*)&Ws[r][cs + 4 * i] = w;
        }
        __syncthreads();
        #pragma unroll
        for (int kc = 0; kc < 4; kc++) {
            float a[2][4];
            #pragma unroll
            for (int mt = 0; mt < 2; mt++) {
                int row = wq * 32 + mt * 16 + lg;
                a[mt][0] = As[row][kc * 8 + lr];
                a[mt][1] = As[row + 8][kc * 8 + lr];
                a[mt][2] = As[row][kc * 8 + lr + 4];
                a[mt][3] = As[row + 8][kc * 8 + lr + 4];
            }
            #pragma unroll
            for (int nt = 0; nt < 4; nt++) {
                int nrow = wn * 32 + nt * 8 + lg;
                float b0 = Ws[nrow][kc * 8 + lr];
                float b1 = Ws[nrow][kc * 8 + lr + 4];
                mma8(acc[0][nt], a[0][0], a[0][1], a[0][2], a[0][3], b0, b1);
                mma8(acc[1][nt], a[1][0], a[1][1], a[1][2], a[1][3], b0, b1);
            }
        }
    }
    #pragma unroll
    for (int mt = 0; mt < 2; mt++)
        #pragma unroll
        for (int nt = 0; nt < 4; nt++)
            #pragma unroll
            for (int hi = 0; hi < 2; hi++) {
                int row = m0 + wq * 32 + mt * 16 + lg + hi * 8;
                int col = n0 + wn * 32 + nt * 8 + 2 * lr;
                float2 o;
                o.x = (acc[mt][nt][hi * 2] + bias[col]) * scale;
                o.y = (acc[mt][nt][hi * 2 + 1] + bias[col + 1]) * scale;
                if (resid) {
                    o.x += resid[(size_t)row * Nd + col];
                    o.y += resid[(size_t)row * Nd + col + 1];
                }
                *(float2*)(Out + (size_t)row * Nd + col) = o;
            }
}

// pass1: S matmul once, p=exp2(S) -> fp16 stash + rowsums.
// pass2: vectorized readback, normalize -> attn_vis, mask -> Ps(bf16), PV(bf16 mma).
__global__ __launch_bounds__(256) void attn_kernel(float* __restrict__ attn_vis) {
    const int h = blockIdx.x, qt = blockIdx.y, b = blockIdx.z;
    const int q0 = qt * 64;
    const int tid = threadIdx.x, warp = tid >> 5, lane = tid & 31;
    const int wq = warp >> 2, wk = warp & 3;
    const int lg = lane >> 2, lr = lane & 3;

    struct SmemP1 { float Ks[128][36]; };
    struct SmemP2 { __nv_bfloat16 VsT[32][136]; __nv_bfloat16 Ps[64][136]; };
    __shared__ union { SmemP1 p1; SmemP2 p2; } sm;
    __shared__ float rsum[64];
    __shared__ float rinv_s[64];

    // Q fragments to registers
    float qa[4][2][4];
    {
        const float* Qbase = g_q + (size_t)(b * Nc + q0 + wq * 32) * Cc + h * Dhc;
        #pragma unroll
        for (int kc = 0; kc < 4; kc++)
            #pragma unroll
            for (int mt = 0; mt < 2; mt++)
                #pragma unroll
                for (int j = 0; j < 4; j++) {
                    int row = mt * 16 + lg + (j & 1) * 8;
                    int col = kc * 8 + lr + (j >> 1) * 4;
                    qa[kc][mt][j] = to_tf32(Qbase[(size_t)row * Cc + col]);
                }
    }
    if (tid < 64) rsum[tid] = 0.f;

    const float* Kb = g_k + (size_t)b * Nc * Cc + h * Dhc;
    const float* Vb = g_v + (size_t)b * Nc * Cc + h * Dhc;
    const int r2 = tid >> 1, cs = (tid & 1) * 16;

    __half* gp_blk = g_p + ((size_t)(b * Hc + h) * Nc + q0) * Nc;
    float psum[4] = {0.f, 0.f, 0.f, 0.f};

    // ================= PASS 1 =================
    for (int kt = 0; kt < Nc / 128; kt++) {
        __syncthreads();
        {
            const float4* sk = (const float4*)(Kb + (size_t)(kt * 128 + r2) * Cc + cs);
            #pragma unroll
            for (int i = 0; i < 4; i++) {
                float4 v = sk[i];
                v.x = to_tf32(v.x); v.y = to_tf32(v.y); v.z = to_tf32(v.z); v.w = to_tf32(v.w);
                *(float4*)&sm.p1.Ks[r2][cs + 4 * i] = v;
            }
        }
        __syncthreads();
        float acc[2][4][4];
        #pragma unroll
        for (int a = 0; a < 2; a++)
            #pragma unroll
            for (int bb = 0; bb < 4; bb++)
                #pragma unroll
                for (int c = 0; c < 4; c++) acc[a][bb][c] = 0.f;
        #pragma unroll
        for (int kc = 0; kc < 4; kc++)
            #pragma unroll
            for (int nt = 0; nt < 4; nt++) {
                int nrow = wk * 32 + nt * 8 + lg;
                float b0 = sm.p1.Ks[nrow][kc * 8 + lr];
                float b1 = sm.p1.Ks[nrow][kc * 8 + lr + 4];
                mma8(acc[0][nt], qa[kc][0][0], qa[kc][0][1], qa[kc][0][2], qa[kc][0][3], b0, b1);
                mma8(acc[1][nt], qa[kc][1][0], qa[kc][1][1], qa[kc][1][2], qa[kc][1][3], b0, b1);
            }
        #pragma unroll
        for (int mt = 0; mt < 2; mt++)
            #pragma unroll
            for (int nt = 0; nt < 4; nt++)
                #pragma unroll
                for (int hi = 0; hi < 2; hi++) {
                    int row = wq * 32 + mt * 16 + lg + hi * 8;
                    int col = wk * 32 + nt * 8 + 2 * lr;
                    int kg = kt * 128 + col;
                    float p0 = ex2f(acc[mt][nt][hi * 2]);
                    float p1 = ex2f(acc[mt][nt][hi * 2 + 1]);
                    psum[mt * 2 + hi] += p0 + p1;
                    *(__half2*)(gp_blk + (size_t)row * Nc + kg) =
                        __floats2half2_rn(p0, p1);
                }
    }
    __syncthreads();
    #pragma unroll
    for (int j = 0; j < 4; j++) {
        float v = psum[j];
        v += __shfl_xor_sync(0xffffffffu, v, 1);
        v += __shfl_xor_sync(0xffffffffu, v, 2);
        if (lr == 0) atomicAdd(&rsum[wq * 32 + (j >> 1) * 16 + lg + (j & 1) * 8], v);
    }
    __syncthreads();
    if (tid < 64) rinv_s[tid] = 1.0f / rsum[tid];
    __syncthreads();

    float xacc[2][4];
    #pragma unroll
    for (int a = 0; a < 2; a++)
        #pragma unroll
        for (int c = 0; c < 4; c++) xacc[a][c] = 0.f;

    const float* mtb = g_maskT + (size_t)b * Nc * Nc;
    float* av = attn_vis + (size_t)(b * Hc + h) * Nc * Nc;
    const int qs = warp >> 1;
    const int dh = (warp & 1) * 16;
    const int r3 = tid >> 2, c3 = (tid & 3) * 32;

    // ================= PASS 2 =================
    for (int kt = 0; kt < Nc / 128; kt++) {
        __syncthreads();
        // V tile -> VsT (bf16, transposed)
        {
            const float4* sv = (const float4*)(Vb + (size_t)(kt * 128 + r2) * Cc + cs);
            #pragma unroll
            for (int i = 0; i < 4; i++) {
                float4 w = sv[i];
                sm.p2.VsT[cs + 4 * i + 0][r2] = __float2bfloat16(w.x);
                sm.p2.VsT[cs + 4 * i + 1][r2] = __float2bfloat16(w.y);
                sm.p2.VsT[cs + 4 * i + 2][r2] = __float2bfloat16(w.z);
                sm.p2.VsT[cs + 4 * i + 3][r2] = __float2bfloat16(w.w);
            }
        }
        // elementwise: p -> attn_vis (fp32) and Ps (bf16, masked)
        {
            const float rv = rinv_s[r3];
            const __half* prow = gp_blk + (size_t)r3 * Nc + kt * 128 + c3;
            const float* mrow = mtb + (size_t)(q0 + r3) * Nc + kt * 128 + c3;
            float* arow = av + (size_t)(q0 + r3) * Nc + kt * 128 + c3;
            #pragma unroll
            for (int j = 0; j < 4; j++) {
                uint4 praw = *(const uint4*)(prow + j * 8);
                float2 f0 = __half22float2(*(const __half2*)&praw.x);
                float2 f1 = __half22float2(*(const __half2*)&praw.y);
                float2 f2 = __half22float2(*(const __half2*)&praw.z);
                float2 f3 = __half22float2(*(const __half2*)&praw.w);
                float a0 = f0.x * rv, a1 = f0.y * rv, a2 = f1.x * rv, a3 = f1.y * rv;
                float a4 = f2.x * rv, a5 = f2.y * rv, a6 = f3.x * rv, a7 = f3.y * rv;
                *(float4*)(arow + j * 8)     = make_float4(a0, a1, a2, a3);
                *(float4*)(arow + j * 8 + 4) = make_float4(a4, a5, a6, a7);
                float4 m0 = *(const float4*)(mrow + j * 8);
                float4 m1 = *(const float4*)(mrow + j * 8 + 4);
                __nv_bfloat162 b0 = __floats2bfloat162_rn(a0 * m0.x, a1 * m0.y);
                __nv_bfloat162 b1 = __floats2bfloat162_rn(a2 * m0.z, a3 * m0.w);
                __nv_bfloat162 b2 = __floats2bfloat162_rn(a4 * m1.x, a5 * m1.y);
                __nv_bfloat162 b3 = __floats2bfloat162_rn(a6 * m1.z, a7 * m1.w);
                uint4 pk;
                pk.x = *(unsigned*)&b0; pk.y = *(unsigned*)&b1;
                pk.z = *(unsigned*)&b2; pk.w = *(unsigned*)&b3;
                *(uint4*)&sm.p2.Ps[r3][c3 + j * 8] = pk;
            }
        }
        __syncthreads();
        // PV: xacc += Ps[64x128] * V[128x32]
        #pragma unroll
        for (int kc = 0; kc < 8; kc++) {
            int prow2 = qs * 16 + lg;
            unsigned a0 = *(const unsigned*)&sm.p2.Ps[prow2][kc * 16 + 2 * lr];
            unsigned a1 = *(const unsigned*)&sm.p2.Ps[prow2 + 8][kc * 16 + 2 * lr];
            unsigned a2 = *(const unsigned*)&sm.p2.Ps[prow2][kc * 16 + 2 * lr + 8];
            unsigned a3 = *(const unsigned*)&sm.p2.Ps[prow2 + 8][kc * 16 + 2 * lr + 8];
            #pragma unroll
            for (int nt = 0; nt < 2; nt++) {
                int n = dh + nt * 8 + lg;
                unsigned b0 = *(const unsigned*)&sm.p2.VsT[n][kc * 16 + 2 * lr];
                unsigned b1 = *(const unsigned*)&sm.p2.VsT[n][kc * 16 + 2 * lr + 8];
                mma16bf(xacc[nt], a0, a1, a2, a3, b0, b1);
            }
        }
    }
    #pragma unroll
    for (int nt = 0; nt < 2; nt++)
        #pragma unroll
        for (int hi = 0; hi < 2; hi++) {
            int row = q0 + qs * 16 + lg + hi * 8;
            int col = h * Dhc + dh + nt * 8 + 2 * lr;
            *(float2*)(g_x + (size_t)(b * Nc + row) * Cc + col) =
                make_float2(xacc[nt][hi * 2], xacc[nt][hi * 2 + 1]);
        }
}

extern "C" void kernel_launch(void* const* d_in, const int* in_sizes, int n_in,
                              void* d_out, int out_size) {
    const float* query = (const float*)d_in[0];
    const float* amask = (const float*)d_in[1];
    const float* Wq = (const float*)d_in[2];
    const float* bq = (const float*)d_in[3];
    const float* Wk = (const float*)d_in[4];
    const float* bk = (const float*)d_in[5];
    const float* Wv = (const float*)d_in[6];
    const float* bv = (const float*)d_in[7];
    const float* Wo = (const float*)d_in[8];
    const float* bo = (const float*)d_in[9];

    float* out = (float*)d_out;
    float* attn_vis = out + (size_t)Bc * Nc * Cc;

    const float QS = 0.17677669529663687f * 1.4426950408889634f;  // SCALE * log2(e)

    dim3 gg(Bc * Nc / 64, Cc / 64);
    init_kernel<<<1, 256>>>();                                   // launch 1 (filler)
    mask_prep_kernel<<<dim3(Nc / 64, Bc), 256>>>(amask);         // launch 2
    gemm_kernel<<<gg, 128>>>(query, -1, Wq, bq, nullptr, nullptr, 0, QS);   // 3
    gemm_kernel<<<gg, 128>>>(query, -1, Wk, bk, nullptr, nullptr, 1, 1.0f); // 4
    gemm_kernel<<<gg, 128>>>(query, -1, Wv, bv, nullptr, nullptr, 2, 1.0f); // 5
    attn_kernel<<<dim3(Hc, Nc / 64, Bc), 256>>>(attn_vis);       // launch 6 -> profiled
    gemm_kernel<<<gg, 128>>>(nullptr, 3, Wo, bo, query, out, -1, 1.0f);     // 7
}

// round 9
// speedup vs baseline: 1.3164x; 1.3164x over previous
#include <cuda_runtime.h>
#include <cuda_bf16.h>
#include <math.h>

#define Bc  4
#define Nc  2048
#define Cc  256
#define Hc  8
#define Dhc 32

__device__ float g_q[Bc * Nc * Cc];
__device__ float g_k[Bc * Nc * Cc];
__device__ float g_v[Bc * Nc * Cc];
__device__ float g_x[Bc * Nc * Cc];
__device__ float g_maskT[(size_t)Bc * Nc * Nc];

__device__ __forceinline__ float to_tf32(float x) {
    asm("cvt.rna.tf32.f32 %0, %1;" : "=f"(x) : "f"(x));
    return x;
}
__device__ __forceinline__ float ex2f(float x) {
    float y;
    asm("ex2.approx.ftz.f32 %0, %1;" : "=f"(y) : "f"(x));
    return y;
}
__device__ __forceinline__ void mma8(float d[4], float a0, float a1, float a2, float a3,
                                     float b0, float b1) {
    asm volatile(
        "mma.sync.aligned.m16n8k8.row.col.f32.tf32.tf32.f32 "
        "{%0,%1,%2,%3}, {%4,%5,%6,%7}, {%8,%9}, {%0,%1,%2,%3};"
        : "+f"(d[0]), "+f"(d[1]), "+f"(d[2]), "+f"(d[3])
        : "r"(__float_as_uint(a0)), "r"(__float_as_uint(a1)),
          "r"(__float_as_uint(a2)), "r"(__float_as_uint(a3)),
          "r"(__float_as_uint(b0)), "r"(__float_as_uint(b1)));
}
__device__ __forceinline__ void mma16bf(float d[4], unsigned a0, unsigned a1, unsigned a2,
                                        unsigned a3, unsigned b0, unsigned b1) {
    asm volatile(
        "mma.sync.aligned.m16n8k16.row.col.f32.bf16.bf16.f32 "
        "{%0,%1,%2,%3}, {%4,%5,%6,%7}, {%8,%9}, {%0,%1,%2,%3};"
        : "+f"(d[0]), "+f"(d[1]), "+f"(d[2]), "+f"(d[3])
        : "r"(a0), "r"(a1), "r"(a2), "r"(a3), "r"(b0), "r"(b1));
}
__device__ __forceinline__ float* bufsel(int s) {
    switch (s) {
        case 0: return g_q;
        case 1: return g_k;
        case 2: return g_v;
        default: return g_x;
    }
}

// maskT[b][q][k] = mask[b][k][q] / max_k mask[b][k][q]
__global__ __launch_bounds__(256) void mask_prep_kernel(const float* __restrict__ mask) {
    const int qt = blockIdx.x, b = blockIdx.y;
    const int q0 = qt * 64, t = threadIdx.x;
    __shared__ float red[4][64];
    __shared__ float cinv[64];
    __shared__ float ts[64][65];
    const int qj = t & 63, kr = t >> 6;
    const float* mb = mask + (size_t)b * Nc * Nc;

    float lmax = 0.f;
    for (int k = kr; k < Nc; k += 4)
        lmax = fmaxf(lmax, mb[(size_t)k * Nc + q0 + qj]);
    red[kr][qj] = lmax;
    __syncthreads();
    if (t < 64)
        cinv[t] = 1.0f / fmaxf(fmaxf(red[0][t], red[1][t]), fmaxf(red[2][t], red[3][t]));
    __syncthreads();

    float* mtb = g_maskT + (size_t)b * Nc * Nc;
    for (int k0 = 0; k0 < Nc; k0 += 64) {
        #pragma unroll 4
        for (int ii = 0; ii < 16; ii++) {
            int i = kr + 4 * ii;
            ts[i][qj] = mb[(size_t)(k0 + i) * Nc + q0 + qj];
        }
        __syncthreads();
        #pragma unroll 4
        for (int jj = 0; jj < 16; jj++) {
            int j = kr + 4 * jj;
            mtb[(size_t)(q0 + j) * Nc + k0 + qj] = ts[qj][j] * cinv[j];
        }
        __syncthreads();
    }
}

// Out[m][n] = (sum_k A[m][k]*W[n][k] + bias[n])*scale + resid[m][n]
__global__ __launch_bounds__(128) void gemm_kernel(
    const float* __restrict__ Aext, int asel,
    const float* __restrict__ W, const float* __restrict__ bias,
    const float* __restrict__ resid,
    float* __restrict__ Oext, int osel, float scale)
{
    const int Kd = Cc, Nd = Cc;
    const float* A = (asel >= 0) ? bufsel(asel) : Aext;
    float* Out = (osel >= 0) ? bufsel(osel) : Oext;

    const int m0 = blockIdx.x * 64, n0 = blockIdx.y * 64;
    __shared__ float As[64][36];
    __shared__ float Ws[64][36];
    const int tid = threadIdx.x, warp = tid >> 5, lane = tid & 31;
    const int wq = warp >> 1, wn = warp & 1, lg = lane >> 2, lr = lane & 3;
    const int r = tid >> 1, cs = (tid & 1) * 16;

    float acc[2][4][4];
    #pragma unroll
    for (int a = 0; a < 2; a++)
        #pragma unroll
        for (int bb = 0; bb < 4; bb++)
            #pragma unroll
            for (int c = 0; c < 4; c++) acc[a][bb][c] = 0.f;

    for (int k0 = 0; k0 < Kd; k0 += 32) {
        __syncthreads();
        const float4* pa = (const float4*)(A + (size_t)(m0 + r) * Kd + k0 + cs);
        const float4* pw = (const float4*)(W + (size_t)(n0 + r) * Kd + k0 + cs);
        #pragma unroll
        for (int i = 0; i < 4; i++) {
            float4 v = pa[i];
            v.x = to_tf32(v.x); v.y = to_tf32(v.y); v.z = to_tf32(v.z); v.w = to_tf32(v.w);
            *(float4*)&As[r][cs + 4 * i] = v;
            float4 w = pw[i];
            w.x = to_tf32(w.x); w.y = to_tf32(w.y); w.z = to_tf32(w.z); w.w = to_tf32(w.w);
            *(float4*)&Ws[r][cs + 4 * i] = w;
        }
        __syncthreads();
        #pragma unroll
        for (int kc = 0; kc < 4; kc++) {
            float a[2][4];
            #pragma unroll
            for (int mt = 0; mt < 2; mt++) {
                int row = wq * 32 + mt * 16 + lg;
                a[mt][0] = As[row][kc * 8 + lr];
                a[mt][1] = As[row + 8][kc * 8 + lr];
                a[mt][2] = As[row][kc * 8 + lr + 4];
                a[mt][3] = As[row + 8][kc * 8 + lr + 4];
            }
            #pragma unroll
            for (int nt = 0; nt < 4; nt++) {
                int nrow = wn * 32 + nt * 8 + lg;
                float b0 = Ws[nrow][kc * 8 + lr];
                float b1 = Ws[nrow][kc * 8 + lr + 4];
                mma8(acc[0][nt], a[0][0], a[0][1], a[0][2], a[0][3], b0, b1);
                mma8(acc[1][nt], a[1][0], a[1][1], a[1][2], a[1][3], b0, b1);
            }
        }
    }
    #pragma unroll
    for (int mt = 0; mt < 2; mt++)
        #pragma unroll
        for (int nt = 0; nt < 4; nt++)
            #pragma unroll
            for (int hi = 0; hi < 2; hi++) {
                int row = m0 + wq * 32 + mt * 16 + lg + hi * 8;
                int col = n0 + wn * 32 + nt * 8 + 2 * lr;
                float2 o;
                o.x = (acc[mt][nt][hi * 2] + bias[col]) * scale;
                o.y = (acc[mt][nt][hi * 2 + 1] + bias[col + 1]) * scale;
                if (resid) {
                    o.x += resid[(size_t)row * Nd + col];
                    o.y += resid[(size_t)row * Nd + col + 1];
                }
                *(float2*)(Out + (size_t)row * Nd + col) = o;
            }
}

// dynamic smem layout (pass 2):
//   Ks  : float[128][36]          @ 0       (18432 B)  -- also pass 1
//   VsT : bf16 [32][136]          @ 18432   ( 8704 B)
//   Ms  : bf16 [64][136]          @ 27136   (17408 B)
//   Ps  : bf16 [64][136]          @ 44544   (17408 B)
//   Pf  : float[64][132]          @ 61952   (33792 B)
//   total 95744 B
#define ATTN_SMEM 95744

__global__ __launch_bounds__(256) void attn_kernel(float* __restrict__ attn_vis) {
    extern __shared__ char dsm[];
    float (*Ks)[36] = reinterpret_cast<float(*)[36]>(dsm);
    __nv_bfloat16 (*VsT)[136] = reinterpret_cast<__nv_bfloat16(*)[136]>(dsm + 18432);
    __nv_bfloat16 (*Ms)[136]  = reinterpret_cast<__nv_bfloat16(*)[136]>(dsm + 27136);
    __nv_bfloat16 (*Ps)[136]  = reinterpret_cast<__nv_bfloat16(*)[136]>(dsm + 44544);
    float (*Pf)[132] = reinterpret_cast<float(*)[132]>(dsm + 61952);
    __shared__ float rsum[64];
    __shared__ float rinv_s[64];

    const int h = blockIdx.x, qt = blockIdx.y, b = blockIdx.z;
    const int q0 = qt * 64;
    const int tid = threadIdx.x, warp = tid >> 5, lane = tid & 31;
    const int wq = warp >> 2, wk = warp & 3;
    const int lg = lane >> 2, lr = lane & 3;

    // Q fragments to registers
    float qa[4][2][4];
    {
        const float* Qbase = g_q + (size_t)(b * Nc + q0 + wq * 32) * Cc + h * Dhc;
        #pragma unroll
        for (int kc = 0; kc < 4; kc++)
            #pragma unroll
            for (int mt = 0; mt < 2; mt++)
                #pragma unroll
                for (int j = 0; j < 4; j++) {
                    int row = mt * 16 + lg + (j & 1) * 8;
                    int col = kc * 8 + lr + (j >> 1) * 4;
                    qa[kc][mt][j] = to_tf32(Qbase[(size_t)row * Cc + col]);
                }
    }
    if (tid < 64) rsum[tid] = 0.f;

    const float* Kb = g_k + (size_t)b * Nc * Cc + h * Dhc;
    const float* Vb = g_v + (size_t)b * Nc * Cc + h * Dhc;
    const int r2 = tid >> 1, cs = (tid & 1) * 16;

    float psum[4] = {0.f, 0.f, 0.f, 0.f};

    // ================= PASS 1: rowsums of exp2(S) =================
    for (int kt = 0; kt < Nc / 128; kt++) {
        __syncthreads();
        {
            const float4* sk = (const float4*)(Kb + (size_t)(kt * 128 + r2) * Cc + cs);
            #pragma unroll
            for (int i = 0; i < 4; i++) {
                float4 v = sk[i];
                v.x = to_tf32(v.x); v.y = to_tf32(v.y); v.z = to_tf32(v.z); v.w = to_tf32(v.w);
                *(float4*)&Ks[r2][cs + 4 * i] = v;
            }
        }
        __syncthreads();
        float acc[2][4][4];
        #pragma unroll
        for (int a = 0; a < 2; a++)
            #pragma unroll
            for (int bb = 0; bb < 4; bb++)
                #pragma unroll
                for (int c = 0; c < 4; c++) acc[a][bb][c] = 0.f;
        #pragma unroll
        for (int kc = 0; kc < 4; kc++)
            #pragma unroll
            for (int nt = 0; nt < 4; nt++) {
                int nrow = wk * 32 + nt * 8 + lg;
                float b0 = Ks[nrow][kc * 8 + lr];
                float b1 = Ks[nrow][kc * 8 + lr + 4];
                mma8(acc[0][nt], qa[kc][0][0], qa[kc][0][1], qa[kc][0][2], qa[kc][0][3], b0, b1);
                mma8(acc[1][nt], qa[kc][1][0], qa[kc][1][1], qa[kc][1][2], qa[kc][1][3], b0, b1);
            }
        #pragma unroll
        for (int mt = 0; mt < 2; mt++)
            #pragma unroll
            for (int nt = 0; nt < 4; nt++)
                #pragma unroll
                for (int i2 = 0; i2 < 4; i2++)
                    psum[mt * 2 + (i2 >> 1)] += ex2f(acc[mt][nt][i2]);
    }
    __syncthreads();
    #pragma unroll
    for (int j = 0; j < 4; j++) {
        float v = psum[j];
        v += __shfl_xor_sync(0xffffffffu, v, 1);
        v += __shfl_xor_sync(0xffffffffu, v, 2);
        if (lr == 0) atomicAdd(&rsum[wq * 32 + (j >> 1) * 16 + lg + (j & 1) * 8], v);
    }
    __syncthreads();
    if (tid < 64) rinv_s[tid] = 1.0f / rsum[tid];
    __syncthreads();

    float xacc[2][4];
    #pragma unroll
    for (int a = 0; a < 2; a++)
        #pragma unroll
        for (int c = 0; c < 4; c++) xacc[a][c] = 0.f;

    const float* mtb = g_maskT + (size_t)b * Nc * Nc;
    float* av = attn_vis + (size_t)(b * Hc + h) * Nc * Nc;
    const int qs = warp >> 1;
    const int dh = (warp & 1) * 16;

    // ================= PASS 2 =================
    for (int kt = 0; kt < Nc / 128; kt++) {
        __syncthreads();
        // K tile (tf32) + V tile (bf16 transposed)
        {
            const float4* sk = (const float4*)(Kb + (size_t)(kt * 128 + r2) * Cc + cs);
            const float4* sv = (const float4*)(Vb + (size_t)(kt * 128 + r2) * Cc + cs);
            #pragma unroll
            for (int i = 0; i < 4; i++) {
                float4 v = sk[i];
                v.x = to_tf32(v.x); v.y = to_tf32(v.y); v.z = to_tf32(v.z); v.w = to_tf32(v.w);
                *(float4*)&Ks[r2][cs + 4 * i] = v;
                float4 w = sv[i];
                VsT[cs + 4 * i + 0][r2] = __float2bfloat16(w.x);
                VsT[cs + 4 * i + 1][r2] = __float2bfloat16(w.y);
                VsT[cs + 4 * i + 2][r2] = __float2bfloat16(w.z);
                VsT[cs + 4 * i + 3][r2] = __float2bfloat16(w.w);
            }
        }
        // maskT tile -> Ms (bf16), fully coalesced rows (512 B per warp-instr)
        {
            #pragma unroll
            for (int i = 0; i < 8; i++) {
                int row = warp * 8 + i;
                float4 m = *(const float4*)(mtb + (size_t)(q0 + row) * Nc + kt * 128 + 4 * lane);
                __nv_bfloat162 u0 = __floats2bfloat162_rn(m.x, m.y);
                __nv_bfloat162 u1 = __floats2bfloat162_rn(m.z, m.w);
                uint2 pk;
                pk.x = *(unsigned*)&u0;
                pk.y = *(unsigned*)&u1;
                *(uint2*)&Ms[row][4 * lane] = pk;
            }
        }
        __syncthreads();
        // S recompute
        float acc[2][4][4];
        #pragma unroll
        for (int a = 0; a < 2; a++)
            #pragma unroll
            for (int bb = 0; bb < 4; bb++)
                #pragma unroll
                for (int c = 0; c < 4; c++) acc[a][bb][c] = 0.f;
        #pragma unroll
        for (int kc = 0; kc < 4; kc++)
            #pragma unroll
            for (int nt = 0; nt < 4; nt++) {
                int nrow = wk * 32 + nt * 8 + lg;
                float b0 = Ks[nrow][kc * 8 + lr];
                float b1 = Ks[nrow][kc * 8 + lr + 4];
                mma8(acc[0][nt], qa[kc][0][0], qa[kc][0][1], qa[kc][0][2], qa[kc][0][3], b0, b1);
                mma8(acc[1][nt], qa[kc][1][0], qa[kc][1][1], qa[kc][1][2], qa[kc][1][3], b0, b1);
            }
        // epilogue: normalized p -> Pf (fp32 smem), masked p -> Ps (bf16 smem)
        #pragma unroll
        for (int mt = 0; mt < 2; mt++)
            #pragma unroll
            for (int nt = 0; nt < 4; nt++)
                #pragma unroll
                for (int hi = 0; hi < 2; hi++) {
                    int row = wq * 32 + mt * 16 + lg + hi * 8;
                    int col = wk * 32 + nt * 8 + 2 * lr;
                    float rv = rinv_s[row];
                    float p0 = ex2f(acc[mt][nt][hi * 2]) * rv;
                    float p1 = ex2f(acc[mt][nt][hi * 2 + 1]) * rv;
                    *(float2*)&Pf[row][col] = make_float2(p0, p1);
                    __nv_bfloat162 mm = *(__nv_bfloat162*)&Ms[row][col];
                    __nv_bfloat162 pm = __floats2bfloat162_rn(
                        p0 * __bfloat162float(mm.x), p1 * __bfloat162float(mm.y));
                    *(__nv_bfloat162*)&Ps[row][col] = pm;
                }
        __syncthreads();
        // coalesced attn_vis store: warp owns 8 rows, 512 B contiguous per instr
        #pragma unroll
        for (int i = 0; i < 8; i++) {
            int row = warp * 8 + i;
            float4 p = *(const float4*)&Pf[row][4 * lane];
            *(float4*)(av + (size_t)(q0 + row) * Nc + kt * 128 + 4 * lane) = p;
        }
        // PV: xacc += Ps[64x128] * V[128x32]
        #pragma unroll
        for (int kc = 0; kc < 8; kc++) {
            int prow = qs * 16 + lg;
            unsigned a0 = *(const unsigned*)&Ps[prow][kc * 16 + 2 * lr];
            unsigned a1 = *(const unsigned*)&Ps[prow + 8][kc * 16 + 2 * lr];
            unsigned a2 = *(const unsigned*)&Ps[prow][kc * 16 + 2 * lr + 8];
            unsigned a3 = *(const unsigned*)&Ps[prow + 8][kc * 16 + 2 * lr + 8];
            #pragma unroll
            for (int nt = 0; nt < 2; nt++) {
                int n = dh + nt * 8 + lg;
                unsigned b0 = *(const unsigned*)&VsT[n][kc * 16 + 2 * lr];
                unsigned b1 = *(const unsigned*)&VsT[n][kc * 16 + 2 * lr + 8];
                mma16bf(xacc[nt], a0, a1, a2, a3, b0, b1);
            }
        }
    }
    #pragma unroll
    for (int nt = 0; nt < 2; nt++)
        #pragma unroll
        for (int hi = 0; hi < 2; hi++) {
            int row = q0 + qs * 16 + lg + hi * 8;
            int col = h * Dhc + dh + nt * 8 + 2 * lr;
            *(float2*)(g_x + (size_t)(b * Nc + row) * Cc + col) =
                make_float2(xacc[nt][hi * 2], xacc[nt][hi * 2 + 1]);
        }
}

extern "C" void kernel_launch(void* const* d_in, const int* in_sizes, int n_in,
                              void* d_out, int out_size) {
    const float* query = (const float*)d_in[0];
    const float* amask = (const float*)d_in[1];
    const float* Wq = (const float*)d_in[2];
    const float* bq = (const float*)d_in[3];
    const float* Wk = (const float*)d_in[4];
    const float* bk = (const float*)d_in[5];
    const float* Wv = (const float*)d_in[6];
    const float* bv = (const float*)d_in[7];
    const float* Wo = (const float*)d_in[8];
    const float* bo = (const float*)d_in[9];

    float* out = (float*)d_out;
    float* attn_vis = out + (size_t)Bc * Nc * Cc;

    const float QS = 0.17677669529663687f * 1.4426950408889634f;  // SCALE * log2(e)

    cudaFuncSetAttribute(attn_kernel, cudaFuncAttributeMaxDynamicSharedMemorySize, ATTN_SMEM);

    dim3 gg(Bc * Nc / 64, Cc / 64);
    mask_prep_kernel<<<dim3(Nc / 64, Bc), 256>>>(amask);
    gemm_kernel<<<gg, 128>>>(query, -1, Wq, bq, nullptr, nullptr, 0, QS);
    gemm_kernel<<<gg, 128>>>(query, -1, Wk, bk, nullptr, nullptr, 1, 1.0f);
    gemm_kernel<<<gg, 128>>>(query, -1, Wv, bv, nullptr, nullptr, 2, 1.0f);
    attn_kernel<<<dim3(Hc, Nc / 64, Bc), 256, ATTN_SMEM>>>(attn_vis);
    gemm_kernel<<<gg, 128>>>(nullptr, 3, Wo, bo, query, out, -1, 1.0f);
}

// round 13
// speedup vs baseline: 1.5429x; 1.1721x over previous
#include <cuda_runtime.h>
#include <cuda_bf16.h>
#include <math.h>

#define Bc  4
#define Nc  2048
#define Cc  256
#define Hc  8
#define Dhc 32

__device__ float g_q[Bc * Nc * Cc];
__device__ float g_x[Bc * Nc * Cc];
__device__ __nv_bfloat16 g_kb[Bc * Nc * Cc];
__device__ __nv_bfloat16 g_vb[Bc * Nc * Cc];
__device__ __nv_bfloat16 g_mb[(size_t)Bc * Nc * Nc];   // maskT bf16

__device__ __forceinline__ float to_tf32(float x) {
    asm("cvt.rna.tf32.f32 %0, %1;" : "=f"(x) : "f"(x));
    return x;
}
__device__ __forceinline__ float ex2f(float x) {
    float y;
    asm("ex2.approx.ftz.f32 %0, %1;" : "=f"(y) : "f"(x));
    return y;
}
__device__ __forceinline__ unsigned pk(float x, float y) {
    __nv_bfloat162 t = __floats2bfloat162_rn(x, y);
    return *(unsigned*)&t;
}
__device__ __forceinline__ void mma8(float d[4], float a0, float a1, float a2, float a3,
                                     float b0, float b1) {
    asm volatile(
        "mma.sync.aligned.m16n8k8.row.col.f32.tf32.tf32.f32 "
        "{%0,%1,%2,%3}, {%4,%5,%6,%7}, {%8,%9}, {%0,%1,%2,%3};"
        : "+f"(d[0]), "+f"(d[1]), "+f"(d[2]), "+f"(d[3])
        : "r"(__float_as_uint(a0)), "r"(__float_as_uint(a1)),
          "r"(__float_as_uint(a2)), "r"(__float_as_uint(a3)),
          "r"(__float_as_uint(b0)), "r"(__float_as_uint(b1)));
}
__device__ __forceinline__ void mma16bf(float d[4], unsigned a0, unsigned a1, unsigned a2,
                                        unsigned a3, unsigned b0, unsigned b1) {
    asm volatile(
        "mma.sync.aligned.m16n8k16.row.col.f32.bf16.bf16.f32 "
        "{%0,%1,%2,%3}, {%4,%5,%6,%7}, {%8,%9}, {%0,%1,%2,%3};"
        : "+f"(d[0]), "+f"(d[1]), "+f"(d[2]), "+f"(d[3])
        : "r"(a0), "r"(a1), "r"(a2), "r"(a3), "r"(b0), "r"(b1));
}

// maskT_bf16[b][q][k] = mask[b][k][q] / max_k mask[b][k][q]
__global__ __launch_bounds__(256) void mask_prep_kernel(const float* __restrict__ mask) {
    const int qt = blockIdx.x, b = blockIdx.y;
    const int q0 = qt * 64, t = threadIdx.x;
    __shared__ float red[4][64];
    __shared__ float cinv[64];
    __shared__ float ts[64][65];
    const int qj = t & 63, kr = t >> 6;
    const float* mb = mask + (size_t)b * Nc * Nc;

    float lmax = 0.f;
    for (int k = kr; k < Nc; k += 4)
        lmax = fmaxf(lmax, mb[(size_t)k * Nc + q0 + qj]);
    red[kr][qj] = lmax;
    __syncthreads();
    if (t < 64)
        cinv[t] = 1.0f / fmaxf(fmaxf(red[0][t], red[1][t]), fmaxf(red[2][t], red[3][t]));
    __syncthreads();

    __nv_bfloat16* mtb = g_mb + (size_t)b * Nc * Nc;
    for (int k0 = 0; k0 < Nc; k0 += 64) {
        #pragma unroll 4
        for (int ii = 0; ii < 16; ii++) {
            int i = kr + 4 * ii;
            ts[i][qj] = mb[(size_t)(k0 + i) * Nc + q0 + qj];
        }
        __syncthreads();
        #pragma unroll 4
        for (int jj = 0; jj < 16; jj++) {
            int j = kr + 4 * jj;
            mtb[(size_t)(q0 + j) * Nc + k0 + qj] = __float2bfloat16(ts[qj][j] * cinv[j]);
        }
        __syncthreads();
    }
}

// Out[m][n] = (sum_k A[m][k]*W[n][k] + bias[n])*scale (+resid). osel: 0=g_q,1=g_kb(bf16),
// 2=g_vb(bf16), 3=g_x, -1=Oext
__global__ __launch_bounds__(128) void gemm_kernel(
    const float* __restrict__ Aext, int asel,
    const float* __restrict__ W, const float* __restrict__ bias,
    const float* __restrict__ resid,
    float* __restrict__ Oext, int osel, float scale)
{
    const int Kd = Cc, Nd = Cc;
    const float* A = (asel == 3) ? g_x : Aext;
    float* Out = (osel == 0) ? g_q : ((osel == 3) ? g_x : Oext);
    __nv_bfloat16* Outb = (osel == 1) ? g_kb : ((osel == 2) ? g_vb : nullptr);

    const int m0 = blockIdx.x * 64, n0 = blockIdx.y * 64;
    __shared__ float As[64][36];
    __shared__ float Ws[64][36];
    const int tid = threadIdx.x, warp = tid >> 5, lane = tid & 31;
    const int wq = warp >> 1, wn = warp & 1, lg = lane >> 2, lr = lane & 3;
    const int r = tid >> 1, cs = (tid & 1) * 16;

    float acc[2][4][4];
    #pragma unroll
    for (int a = 0; a < 2; a++)
        #pragma unroll
        for (int bb = 0; bb < 4; bb++)
            #pragma unroll
            for (int c = 0; c < 4; c++) acc[a][bb][c] = 0.f;

    for (int k0 = 0; k0 < Kd; k0 += 32) {
        __syncthreads();
        const float4* pa = (const float4*)(A + (size_t)(m0 + r) * Kd + k0 + cs);
        const float4* pw = (const float4*)(W + (size_t)(n0 + r) * Kd + k0 + cs);
        #pragma unroll
        for (int i = 0; i < 4; i++) {
            float4 v = pa[i];
            v.x = to_tf32(v.x); v.y = to_tf32(v.y); v.z = to_tf32(v.z); v.w = to_tf32(v.w);
            *(float4*)&As[r][cs + 4 * i] = v;
            float4 w = pw[i];
            w.x = to_tf32(w.x); w.y = to_tf32(w.y); w.z = to_tf32(w.z); w.w = to_tf32(w.w);
            *(float4*)&Ws[r][cs + 4 * i] = w;
        }
        __syncthreads();
        #pragma unroll
        for (int kc = 0; kc < 4; kc++) {
            float a[2][4];
            #pragma unroll
            for (int mt = 0; mt < 2; mt++) {
                int row = wq * 32 + mt * 16 + lg;
                a[mt][0] = As[row][kc * 8 + lr];
                a[mt][1] = As[row + 8][kc * 8 + lr];
                a[mt][2] = As[row][kc * 8 + lr + 4];
                a[mt][3] = As[row + 8][kc * 8 + lr + 4];
            }
            #pragma unroll
            for (int nt = 0; nt < 4; nt++) {
                int nrow = wn * 32 + nt * 8 + lg;
                float b0 = Ws[nrow][kc * 8 + lr];
                float b1 = Ws[nrow][kc * 8 + lr + 4];
                mma8(acc[0][nt], a[0][0], a[0][1], a[0][2], a[0][3], b0, b1);
                mma8(acc[1][nt], a[1][0], a[1][1], a[1][2], a[1][3], b0, b1);
            }
        }
    }
    #pragma unroll
    for (int mt = 0; mt < 2; mt++)
        #pragma unroll
        for (int nt = 0; nt < 4; nt++)
            #pragma unroll
            for (int hi = 0; hi < 2; hi++) {
                int row = m0 + wq * 32 + mt * 16 + lg + hi * 8;
                int col = n0 + wn * 32 + nt * 8 + 2 * lr;
                float ox = (acc[mt][nt][hi * 2] + bias[col]) * scale;
                float oy = (acc[mt][nt][hi * 2 + 1] + bias[col + 1]) * scale;
                if (Outb) {
                    *(unsigned*)&Outb[(size_t)row * Nd + col] = pk(ox, oy);
                } else {
                    if (resid) {
                        ox += resid[(size_t)row * Nd + col];
                        oy += resid[(size_t)row * Nd + col + 1];
                    }
                    *(float2*)(Out + (size_t)row * Nd + col) = make_float2(ox, oy);
                }
            }
}

// dynamic smem:
//   Ksp  u32 [128][20] @0      (10240)   packed bf16x2 K (channel pairs)
//   VsTp u32 [32][68]  @10240  ( 8704)   packed bf16x2 V^T (token pairs)
//   Msp  u32 [64][68]  @18944  (17408)   packed bf16x2 maskT (k pairs)
//   Psp  u32 [64][68]  @36352  (17408)   packed bf16x2 masked P
//   Pf   f32 [64][136] @53760  (34816)   normalized P staging for coalesced store
#define ATTN_SMEM 88576

__global__ __launch_bounds__(256) void attn_kernel(float* __restrict__ attn_vis) {
    extern __shared__ char dsm[];
    unsigned (*Ksp)[20]  = reinterpret_cast<unsigned(*)[20]>(dsm);
    unsigned (*VsTp)[68] = reinterpret_cast<unsigned(*)[68]>(dsm + 10240);
    unsigned (*Msp)[68]  = reinterpret_cast<unsigned(*)[68]>(dsm + 18944);
    unsigned (*Psp)[68]  = reinterpret_cast<unsigned(*)[68]>(dsm + 36352);
    float (*Pf)[136]     = reinterpret_cast<float(*)[136]>(dsm + 53760);
    __shared__ float rsum[64];
    __shared__ float rinv_s[64];

    const int h = blockIdx.x, qt = blockIdx.y, b = blockIdx.z;
    const int q0 = qt * 64;
    const int tid = threadIdx.x, warp = tid >> 5, lane = tid & 31;
    const int wq = warp >> 2, wk = warp & 3;
    const int lg = lane >> 2, lr = lane & 3;

    // Q fragments -> packed bf16 registers (loaded once)
    unsigned qa[2][2][4];
    {
        const float* Qb = g_q + (size_t)(b * Nc + q0 + wq * 32) * Cc + h * Dhc;
        #pragma unroll
        for (int ks = 0; ks < 2; ks++)
            #pragma unroll
            for (int mt = 0; mt < 2; mt++) {
                int r0 = mt * 16 + lg, k0 = ks * 16 + 2 * lr;
                qa[ks][mt][0] = pk(Qb[(size_t)r0 * Cc + k0],       Qb[(size_t)r0 * Cc + k0 + 1]);
                qa[ks][mt][1] = pk(Qb[(size_t)(r0 + 8) * Cc + k0], Qb[(size_t)(r0 + 8) * Cc + k0 + 1]);
                qa[ks][mt][2] = pk(Qb[(size_t)r0 * Cc + k0 + 8],   Qb[(size_t)r0 * Cc + k0 + 9]);
                qa[ks][mt][3] = pk(Qb[(size_t)(r0 + 8) * Cc + k0 + 8], Qb[(size_t)(r0 + 8) * Cc + k0 + 9]);
            }
    }
    if (tid < 64) rsum[tid] = 0.f;

    const __nv_bfloat16* Kbb = g_kb + (size_t)b * Nc * Cc + h * Dhc;
    const __nv_bfloat16* Vbb = g_vb + (size_t)b * Nc * Cc + h * Dhc;
    const int r2 = tid >> 1, cs16 = (tid & 1) * 16;

    float psum[4] = {0.f, 0.f, 0.f, 0.f};

    // ================= PASS 1: rowsums of exp2(S) =================
    for (int kt = 0; kt < Nc / 128; kt++) {
        __syncthreads();
        {
            const uint4* kv = (const uint4*)(Kbb + (size_t)(kt * 128 + r2) * Cc + cs16);
            uint4 u0 = kv[0], u1 = kv[1];
            *(uint4*)&Ksp[r2][(tid & 1) * 8] = u0;
            *(uint4*)&Ksp[r2][(tid & 1) * 8 + 4] = u1;
        }
        __syncthreads();
        float acc[2][4][4];
        #pragma unroll
        for (int a = 0; a < 2; a++)
            #pragma unroll
            for (int bb = 0; bb < 4; bb++)
                #pragma unroll
                for (int c = 0; c < 4; c++) acc[a][bb][c] = 0.f;
        #pragma unroll
        for (int ks = 0; ks < 2; ks++)
            #pragma unroll
            for (int nt = 0; nt < 4; nt++) {
                int nrow = wk * 32 + nt * 8 + lg;
                unsigned b0 = Ksp[nrow][ks * 8 + lr];
                unsigned b1 = Ksp[nrow][ks * 8 + lr + 4];
                mma16bf(acc[0][nt], qa[ks][0][0], qa[ks][0][1], qa[ks][0][2], qa[ks][0][3], b0, b1);
                mma16bf(acc[1][nt], qa[ks][1][0], qa[ks][1][1], qa[ks][1][2], qa[ks][1][3], b0, b1);
            }
        #pragma unroll
        for (int mt = 0; mt < 2; mt++)
            #pragma unroll
            for (int nt = 0; nt < 4; nt++)
                #pragma unroll
                for (int i2 = 0; i2 < 4; i2++)
                    psum[mt * 2 + (i2 >> 1)] += ex2f(acc[mt][nt][i2]);
    }
    __syncthreads();
    #pragma unroll
    for (int j = 0; j < 4; j++) {
        float v = psum[j];
        v += __shfl_xor_sync(0xffffffffu, v, 1);
        v += __shfl_xor_sync(0xffffffffu, v, 2);
        if (lr == 0) atomicAdd(&rsum[wq * 32 + (j >> 1) * 16 + lg + (j & 1) * 8], v);
    }
    __syncthreads();
    if (tid < 64) rinv_s[tid] = 1.0f / rsum[tid];
    __syncthreads();

    float xacc[2][4];
    #pragma unroll
    for (int a = 0; a < 2; a++)
        #pragma unroll
        for (int c = 0; c < 4; c++) xacc[a][c] = 0.f;

    const __nv_bfloat16* mtb = g_mb + (size_t)b * Nc * Nc;
    float* av = attn_vis + (size_t)(b * Hc + h) * Nc * Nc;
    const int qs = warp >> 1;
    const int dh = (warp & 1) * 16;
    const int vkp = tid & 63, vn0 = (tid >> 6) * 8;
    const int mrow = tid >> 2, mseg = (tid & 3) * 32;

    // ================= PASS 2 =================
    for (int kt = 0; kt < Nc / 128; kt++) {
        __syncthreads();
        // K tile (raw bf16 copy)
        {
            const uint4* kv = (const uint4*)(Kbb + (size_t)(kt * 128 + r2) * Cc + cs16);
            uint4 u0 = kv[0], u1 = kv[1];
            *(uint4*)&Ksp[r2][(tid & 1) * 8] = u0;
            *(uint4*)&Ksp[r2][(tid & 1) * 8 + 4] = u1;
        }
        // V tile -> VsTp (token-pair packed, PRMT transpose)
        {
            const uint4* va = (const uint4*)(Vbb + (size_t)(kt * 128 + 2 * vkp) * Cc + vn0);
            const uint4* vb2 = (const uint4*)(Vbb + (size_t)(kt * 128 + 2 * vkp + 1) * Cc + vn0);
            uint4 A = *va, B2 = *vb2;
            VsTp[vn0 + 0][vkp] = __byte_perm(A.x, B2.x, 0x5410);
            VsTp[vn0 + 1][vkp] = __byte_perm(A.x, B2.x, 0x7632);
            VsTp[vn0 + 2][vkp] = __byte_perm(A.y, B2.y, 0x5410);
            VsTp[vn0 + 3][vkp] = __byte_perm(A.y, B2.y, 0x7632);
            VsTp[vn0 + 4][vkp] = __byte_perm(A.z, B2.z, 0x5410);
            VsTp[vn0 + 5][vkp] = __byte_perm(A.z, B2.z, 0x7632);
            VsTp[vn0 + 6][vkp] = __byte_perm(A.w, B2.w, 0x5410);
            VsTp[vn0 + 7][vkp] = __byte_perm(A.w, B2.w, 0x7632);
        }
        // mask tile (raw bf16 copy)
        {
            const uint4* mm4 = (const uint4*)(mtb + (size_t)(q0 + mrow) * Nc + kt * 128 + mseg);
            uint4 m0 = mm4[0], m1 = mm4[1], m2v = mm4[2], m3 = mm4[3];
            int c0 = mseg >> 1;
            *(uint4*)&Msp[mrow][c0]      = m0;
            *(uint4*)&Msp[mrow][c0 + 4]  = m1;
            *(uint4*)&Msp[mrow][c0 + 8]  = m2v;
            *(uint4*)&Msp[mrow][c0 + 12] = m3;
        }
        __syncthreads();
        // S recompute (bf16)
        float acc[2][4][4];
        #pragma unroll
        for (int a = 0; a < 2; a++)
            #pragma unroll
            for (int bb = 0; bb < 4; bb++)
                #pragma unroll
                for (int c = 0; c < 4; c++) acc[a][bb][c] = 0.f;
        #pragma unroll
        for (int ks = 0; ks < 2; ks++)
            #pragma unroll
            for (int nt = 0; nt < 4; nt++) {
                int nrow = wk * 32 + nt * 8 + lg;
                unsigned b0 = Ksp[nrow][ks * 8 + lr];
                unsigned b1 = Ksp[nrow][ks * 8 + lr + 4];
                mma16bf(acc[0][nt], qa[ks][0][0], qa[ks][0][1], qa[ks][0][2], qa[ks][0][3], b0, b1);
                mma16bf(acc[1][nt], qa[ks][1][0], qa[ks][1][1], qa[ks][1][2], qa[ks][1][3], b0, b1);
            }
        // epilogue: normalized p -> Pf; masked p -> Psp
        #pragma unroll
        for (int mt = 0; mt < 2; mt++)
            #pragma unroll
            for (int nt = 0; nt < 4; nt++)
                #pragma unroll
                for (int hi = 0; hi < 2; hi++) {
                    int row = wq * 32 + mt * 16 + lg + hi * 8;
                    int colp = wk * 16 + nt * 4 + lr;
                    float rv = rinv_s[row];
                    float p0 = ex2f(acc[mt][nt][hi * 2]) * rv;
                    float p1 = ex2f(acc[mt][nt][hi * 2 + 1]) * rv;
                    *(float2*)&Pf[row][2 * colp] = make_float2(p0, p1);
                    unsigned mmv = Msp[row][colp];
                    __nv_bfloat162 mb2 = *(__nv_bfloat162*)&mmv;
                    Psp[row][colp] = pk(p0 * __bfloat162float(mb2.x),
                                        p1 * __bfloat162float(mb2.y));
                }
        __syncthreads();
        // coalesced attn_vis store
        #pragma unroll
        for (int i = 0; i < 8; i++) {
            int row = warp * 8 + i;
            float4 p = *(const float4*)&Pf[row][4 * lane];
            *(float4*)(av + (size_t)(q0 + row) * Nc + kt * 128 + 4 * lane) = p;
        }
        // PV: xacc += P[64x128] * V[128x32]
        #pragma unroll
        for (int kc = 0; kc < 8; kc++) {
            int prow = qs * 16 + lg;
            unsigned a0 = Psp[prow][kc * 8 + lr];
            unsigned a1 = Psp[prow + 8][kc * 8 + lr];
            unsigned a2 = Psp[prow][kc * 8 + lr + 4];
            unsigned a3 = Psp[prow + 8][kc * 8 + lr + 4];
            #pragma unroll
            for (int nt = 0; nt < 2; nt++) {
                int n = dh + nt * 8 + lg;
                unsigned b0 = VsTp[n][kc * 8 + lr];
                unsigned b1 = VsTp[n][kc * 8 + lr + 4];
                mma16bf(xacc[nt], a0, a1, a2, a3, b0, b1);
            }
        }
    }
    #pragma unroll
    for (int nt = 0; nt < 2; nt++)
        #pragma unroll
        for (int hi = 0; hi < 2; hi++) {
            int row = q0 + qs * 16 + lg + hi * 8;
            int col = h * Dhc + dh + nt * 8 + 2 * lr;
            *(float2*)(g_x + (size_t)(b * Nc + row) * Cc + col) =
                make_float2(xacc[nt][hi * 2], xacc[nt][hi * 2 + 1]);
        }
}

extern "C" void kernel_launch(void* const* d_in, const int* in_sizes, int n_in,
                              void* d_out, int out_size) {
    const float* query = (const float*)d_in[0];
    const float* amask = (const float*)d_in[1];
    const float* Wq = (const float*)d_in[2];
    const float* bq = (const float*)d_in[3];
    const float* Wk = (const float*)d_in[4];
    const float* bk = (const float*)d_in[5];
    const float* Wv = (const float*)d_in[6];
    const float* bv = (const float*)d_in[7];
    const float* Wo = (const float*)d_in[8];
    const float* bo = (const float*)d_in[9];

    float* out = (float*)d_out;
    float* attn_vis = out + (size_t)Bc * Nc * Cc;

    const float QS = 0.17677669529663687f * 1.4426950408889634f;  // SCALE * log2(e)

    cudaFuncSetAttribute(attn_kernel, cudaFuncAttributeMaxDynamicSharedMemorySize, ATTN_SMEM);

    dim3 gg(Bc * Nc / 64, Cc / 64);
    mask_prep_kernel<<<dim3(Nc / 64, Bc), 256>>>(amask);
    gemm_kernel<<<gg, 128>>>(query, -1, Wq, bq, nullptr, nullptr, 0, QS);
    gemm_kernel<<<gg, 128>>>(query, -1, Wk, bk, nullptr, nullptr, 1, 1.0f);
    gemm_kernel<<<gg, 128>>>(query, -1, Wv, bv, nullptr, nullptr, 2, 1.0f);
    attn_kernel<<<dim3(Hc, Nc / 64, Bc), 256, ATTN_SMEM>>>(attn_vis);
    gemm_kernel<<<gg, 128>>>(nullptr, 3, Wo, bo, query, out, -1, 1.0f);
}